// round 1
// baseline (speedup 1.0000x reference)
#include <cuda_runtime.h>

// Problem constants (fixed by setup_inputs): B=1, D=128, H=64, W=96,
// NUM_LEVELS=4, RADIUS=4 -> K=81.
#define D128 128
#define H0 64
#define W0 96
#define HW0 (H0 * W0)   // 6144

// Per-map pyramid scratch in (H*W, D) "HWD" layout.
// L0: 6144*128=786432, L1: 196608, L2: 49152, L3: 12288  -> total 1044480 floats
__device__ __align__(16) float g_f1[1044480];
__device__ __align__(16) float g_f2[1044480];

// ---------------------------------------------------------------------------
// Kernel 1: transpose (D, H*W) -> (H*W, D) for both maps. Tiled 32x32.
// ---------------------------------------------------------------------------
__global__ void transpose_kernel(const float* __restrict__ f1,
                                 const float* __restrict__ f2) {
    __shared__ float tile[32][33];
    const float* in  = blockIdx.z ? f2 : f1;
    float*       out = blockIdx.z ? g_f2 : g_f1;
    int pB = blockIdx.x * 32;   // pixel base (0..6143)
    int dB = blockIdx.y * 32;   // channel base (0..127)
    int tx = threadIdx.x, ty = threadIdx.y;
    tile[ty][tx] = in[(dB + ty) * HW0 + pB + tx];
    __syncthreads();
    out[(pB + ty) * D128 + dB + tx] = tile[tx][ty];
}

// ---------------------------------------------------------------------------
// Kernel 2: 2x2 avg pool in HWD layout, both maps (blockIdx.y selects map).
// ---------------------------------------------------------------------------
__global__ void pool_kernel(int inOff, int outOff, int Wi, int Wo, int n) {
    int i = blockIdx.x * 256 + threadIdx.x;
    if (i >= n) return;
    float* base = blockIdx.y ? g_f2 : g_f1;
    int c  = i & 127;
    int pk = i >> 7;
    int wo = pk % Wo, ho = pk / Wo;
    const float* in = base + inOff + ((2 * ho) * Wi + 2 * wo) * D128 + c;
    base[outOff + i] = 0.25f * (in[0] + in[D128] + in[Wi * D128] + in[Wi * D128 + D128]);
}

// ---------------------------------------------------------------------------
// Kernel 3: fused correlation lookup for all 4 levels.
// One 128-thread block per output pixel. blockIdx -> (level, pixel).
// ---------------------------------------------------------------------------
__global__ __launch_bounds__(128) void corr_kernel(const float* __restrict__ coords,
                                                   float* __restrict__ out) {
    int b = blockIdx.x;
    int lvl, p;
    if (b < 6144)       { lvl = 0; p = b; }
    else if (b < 7680)  { lvl = 1; p = b - 6144; }
    else if (b < 8064)  { lvl = 2; p = b - 7680; }
    else                { lvl = 3; p = b - 8064; }

    int loff, ooff;
    switch (lvl) {
        case 0:  loff = 0;       ooff = 0;      break;
        case 1:  loff = 786432;  ooff = 497664; break;
        case 2:  loff = 983040;  ooff = 622080; break;
        default: loff = 1032192; ooff = 653184; break;
    }
    const int Hl = H0 >> lvl, Wl = W0 >> lvl;
    int py = p / Wl, px = p - py * Wl;

    __shared__ float sh_c[2];
    __shared__ __align__(16) float sh_f1[D128];
    __shared__ float sh_dot[100];

    int t = threadIdx.x;

    // --- coords at this level: jax.image.resize(method='linear', antialias=True)
    //     = separable triangle kernel with kernel_scale = 2^lvl, per-dim
    //     normalization over in-range taps; then / 2^lvl.
    if (t < 2) {
        float c;
        if (lvl == 0) {
            c = coords[t * HW0 + p];
        } else {
            int   f    = 1 << lvl;
            float invf = 1.0f / (float)f;
            float sy = ((float)py + 0.5f) * (float)f - 0.5f;
            float sx = ((float)px + 0.5f) * (float)f - 0.5f;
            int jylo = max(0,      (int)floorf(sy - (float)f) + 1);
            int jyhi = min(H0 - 1, (int)floorf(sy + (float)f));
            int jxlo = max(0,      (int)floorf(sx - (float)f) + 1);
            int jxhi = min(W0 - 1, (int)floorf(sx + (float)f));
            float wyTot = 0.f, wxTot = 0.f;
            for (int j = jylo; j <= jyhi; j++) wyTot += 1.f - fabsf(sy - (float)j) * invf;
            for (int j = jxlo; j <= jxhi; j++) wxTot += 1.f - fabsf(sx - (float)j) * invf;
            const float* cc = coords + t * HW0;
            float acc = 0.f;
            for (int jy = jylo; jy <= jyhi; jy++) {
                float wy = 1.f - fabsf(sy - (float)jy) * invf;
                float ra = 0.f;
                for (int jx = jxlo; jx <= jxhi; jx++)
                    ra += (1.f - fabsf(sx - (float)jx) * invf) * cc[jy * W0 + jx];
                acc += wy * ra;
            }
            c = acc / (wyTot * wxTot) * invf;   // resize result, then / 2^lvl
        }
        sh_c[t] = c;
    }

    // --- stage f1 vector for this pixel
    sh_f1[t] = g_f1[loff + p * D128 + t];
    __syncthreads();

    float cx = sh_c[0], cy = sh_c[1];
    int ix = (int)floorf(cx);
    int iy = (int)floorf(cy);

    // --- 10x10 corner dot grid: thread t < 100 owns one integer position
    if (t < 100) {
        int ty = t / 10, tx = t - ty * 10;
        int gy = min(max(iy + ty - 4, 0), Hl - 1);
        int gx = min(max(ix + tx - 4, 0), Wl - 1);
        const float4* f2v = (const float4*)(g_f2 + loff + (gy * Wl + gx) * D128);
        const float4* f1v = (const float4*)sh_f1;
        float s = 0.f;
#pragma unroll
        for (int i = 0; i < 32; i++) {
            float4 a = f1v[i];
            float4 q = f2v[i];
            s += a.x * q.x;
            s += a.y * q.y;
            s += a.z * q.z;
            s += a.w * q.w;
        }
        sh_dot[t] = s;
    }
    __syncthreads();

    // --- bilinear combine for the 81 offsets, k = dxi*9 + dyi (x slow, y fast)
    if (t < 81) {
        int dxi = t / 9, dyi = t - dxi * 9;
        float xq = fminf(fmaxf(cx + (float)(dxi - 4), 0.f), (float)(Wl - 1));
        float yq = fminf(fmaxf(cy + (float)(dyi - 4), 0.f), (float)(Hl - 1));
        float x0f = floorf(xq), y0f = floorf(yq);
        float wx1 = xq - x0f,  wy1 = yq - y0f;
        float wx0 = 1.f - wx1, wy0 = 1.f - wy1;
        // Recover tap indices from the actual floor (handles the rare fp case
        // floor(cx+dx) != floor(cx)+dx; mismatch only occurs with zero weight).
        int t0x = min(max((int)x0f - ix + 4, 0), 9), t1x = min(t0x + 1, 9);
        int t0y = min(max((int)y0f - iy + 4, 0), 9), t1y = min(t0y + 1, 9);
        float v = wy0 * (wx0 * sh_dot[t0y * 10 + t0x] + wx1 * sh_dot[t0y * 10 + t1x])
                + wy1 * (wx0 * sh_dot[t1y * 10 + t0x] + wx1 * sh_dot[t1y * 10 + t1x]);
        out[ooff + t * (Hl * Wl) + p] = v * 0.08838834764831845f;  // 1/sqrt(128)
    }
}

// ---------------------------------------------------------------------------
extern "C" void kernel_launch(void* const* d_in, const int* in_sizes, int n_in,
                              void* d_out, int out_size) {
    const float* f1     = (const float*)d_in[0];
    const float* f2     = (const float*)d_in[1];
    const float* coords = (const float*)d_in[2];
    float* out = (float*)d_out;

    transpose_kernel<<<dim3(HW0 / 32, D128 / 32, 2), dim3(32, 32)>>>(f1, f2);
    // L0(64x96) -> L1(32x48)
    pool_kernel<<<dim3(768, 2), 256>>>(0,       786432,  96, 48, 196608);
    // L1 -> L2(16x24)
    pool_kernel<<<dim3(192, 2), 256>>>(786432,  983040,  48, 24, 49152);
    // L2 -> L3(8x12)
    pool_kernel<<<dim3(48, 2),  256>>>(983040,  1032192, 24, 12, 12288);
    // fused correlation for all levels: 6144+1536+384+96 = 8160 blocks
    corr_kernel<<<8160, 128>>>(coords, out);
}

// round 2
// speedup vs baseline: 2.1055x; 2.1055x over previous
#include <cuda_runtime.h>

// Problem constants (fixed by setup_inputs): B=1, D=128, H=64, W=96,
// NUM_LEVELS=4, RADIUS=4 -> K=81.
#define D128 128
#define H0 64
#define W0 96
#define HW0 (H0 * W0)   // 6144

// Per-map pyramid scratch in (H*W, D) "HWD" layout.
// L0: 786432, L1: 196608, L2: 49152, L3: 12288 -> total 1044480 floats
__device__ __align__(16) float g_f1[1044480];
__device__ __align__(16) float g_f2[1044480];

// ---------------------------------------------------------------------------
// Kernel 1: transpose (D, H*W) -> (H*W, D) for both maps. Tiled 32x32.
// ---------------------------------------------------------------------------
__global__ void transpose_kernel(const float* __restrict__ f1,
                                 const float* __restrict__ f2) {
    __shared__ float tile[32][33];
    const float* in  = blockIdx.z ? f2 : f1;
    float*       out = blockIdx.z ? g_f2 : g_f1;
    int pB = blockIdx.x * 32;   // pixel base
    int dB = blockIdx.y * 32;   // channel base
    int tx = threadIdx.x, ty = threadIdx.y;
    tile[ty][tx] = in[(dB + ty) * HW0 + pB + tx];
    __syncthreads();
    out[(pB + ty) * D128 + dB + tx] = tile[tx][ty];
}

// ---------------------------------------------------------------------------
// Kernel 2: all pooled levels computed directly from transposed L0.
// Levels are mutually independent -> single launch.
// 258048 outputs per map (L1 196608 + L2 49152 + L3 12288), x2 maps.
// ---------------------------------------------------------------------------
__global__ void pool_all_kernel() {
    int i = blockIdx.x * 256 + threadIdx.x;
    if (i >= 2 * 258048) return;
    float* base = (i >= 258048) ? g_f2 : g_f1;
    if (i >= 258048) i -= 258048;

    int lvl, ooff, idx;
    if (i < 196608)      { lvl = 1; ooff = 786432;  idx = i; }
    else if (i < 245760) { lvl = 2; ooff = 983040;  idx = i - 196608; }
    else                 { lvl = 3; ooff = 1032192; idx = i - 245760; }

    int c  = idx & 127;
    int pk = idx >> 7;
    int Wl = W0 >> lvl;
    int wo = pk % Wl, ho = pk / Wl;
    int s  = 1 << lvl;
    const float* in = base + ((ho * s) * W0 + wo * s) * D128 + c;
    float acc = 0.f;
    for (int dy = 0; dy < s; dy++)
        for (int dx = 0; dx < s; dx++)
            acc += in[(dy * W0 + dx) * D128];
    base[ooff + idx] = acc * (1.0f / (float)(s * s));
}

// ---------------------------------------------------------------------------
// Kernel 3: fused correlation lookup for all 4 levels.
// One 128-thread block per output pixel. Coalesced dot phase:
//   each pass, a warp handles 4 positions; 8 lanes cooperatively stream one
//   position's contiguous 128B chunks (4 lines/instr), 3x shfl_xor reduce.
// Block->pixel remap keeps same-SM blocks on contiguous pixels (L1 locality).
// ---------------------------------------------------------------------------
__global__ __launch_bounds__(128) void corr_kernel(const float* __restrict__ coords,
                                                   float* __restrict__ out) {
    // same-SM blocks: bid === r (mod 148). Give them contiguous work ids.
    int g = (blockIdx.x % 148) * 56 + blockIdx.x / 148;
    if (g >= 8160) return;

    int lvl, p;
    if (g < 6144)       { lvl = 0; p = g; }
    else if (g < 7680)  { lvl = 1; p = g - 6144; }
    else if (g < 8064)  { lvl = 2; p = g - 7680; }
    else                { lvl = 3; p = g - 8064; }

    int loff, ooff;
    switch (lvl) {
        case 0:  loff = 0;       ooff = 0;      break;
        case 1:  loff = 786432;  ooff = 497664; break;
        case 2:  loff = 983040;  ooff = 622080; break;
        default: loff = 1032192; ooff = 653184; break;
    }
    const int Hl = H0 >> lvl, Wl = W0 >> lvl;
    int py = p / Wl, px = p - py * Wl;

    __shared__ float sh_c[2];
    __shared__ float sh_dot[112];

    int t    = threadIdx.x;
    int w    = t >> 5;
    int lane = t & 31;
    int sub  = lane & 7;   // chunk-owner within an 8-lane group
    int quad = lane >> 3;  // which of 4 positions this pass

    // --- coords at this level (jax.image.resize linear antialias semantics)
    if (t < 2) {
        float c;
        if (lvl == 0) {
            c = coords[t * HW0 + p];
        } else {
            int   f    = 1 << lvl;
            float invf = 1.0f / (float)f;
            float sy = ((float)py + 0.5f) * (float)f - 0.5f;
            float sx = ((float)px + 0.5f) * (float)f - 0.5f;
            int jylo = max(0,      (int)floorf(sy - (float)f) + 1);
            int jyhi = min(H0 - 1, (int)floorf(sy + (float)f));
            int jxlo = max(0,      (int)floorf(sx - (float)f) + 1);
            int jxhi = min(W0 - 1, (int)floorf(sx + (float)f));
            float wyTot = 0.f, wxTot = 0.f;
            for (int j = jylo; j <= jyhi; j++) wyTot += 1.f - fabsf(sy - (float)j) * invf;
            for (int j = jxlo; j <= jxhi; j++) wxTot += 1.f - fabsf(sx - (float)j) * invf;
            const float* cc = coords + t * HW0;
            float acc = 0.f;
            for (int jy = jylo; jy <= jyhi; jy++) {
                float wy = 1.f - fabsf(sy - (float)jy) * invf;
                float ra = 0.f;
                for (int jx = jxlo; jx <= jxhi; jx++)
                    ra += (1.f - fabsf(sx - (float)jx) * invf) * cc[jy * W0 + jx];
                acc += wy * ra;
            }
            c = acc / (wyTot * wxTot) * invf;
        }
        sh_c[t] = c;
    }

    // --- f1 vector chunks for this lane (each lane owns chunks i*8+sub)
    const float4* f1v = (const float4*)(g_f1 + loff + p * D128);
    float4 a0 = f1v[0 * 8 + sub];
    float4 a1 = f1v[1 * 8 + sub];
    float4 a2 = f1v[2 * 8 + sub];
    float4 a3 = f1v[3 * 8 + sub];

    __syncthreads();

    float cx = sh_c[0], cy = sh_c[1];
    int ix = (int)floorf(cx);
    int iy = (int)floorf(cy);

    const float4* f2base = (const float4*)(g_f2 + loff);

    // --- 100 corner dots: 7 passes x (4 warps x 4 positions)
#pragma unroll
    for (int j = 0; j < 7; j++) {
        int pos  = j * 16 + w * 4 + quad;      // 0..111
        int posc = min(pos, 99);
        int ty = posc / 10, tx = posc - ty * 10;
        int gy = min(max(iy + ty - 4, 0), Hl - 1);
        int gx = min(max(ix + tx - 4, 0), Wl - 1);
        const float4* q = f2base + (gy * Wl + gx) * 32;
        float4 q0 = q[0 * 8 + sub];
        float4 q1 = q[1 * 8 + sub];
        float4 q2 = q[2 * 8 + sub];
        float4 q3 = q[3 * 8 + sub];
        float s = a0.x * q0.x + a0.y * q0.y + a0.z * q0.z + a0.w * q0.w;
        s += a1.x * q1.x + a1.y * q1.y + a1.z * q1.z + a1.w * q1.w;
        s += a2.x * q2.x + a2.y * q2.y + a2.z * q2.z + a2.w * q2.w;
        s += a3.x * q3.x + a3.y * q3.y + a3.z * q3.z + a3.w * q3.w;
        // reduce over the 8 lanes of this position's group
        s += __shfl_xor_sync(0xffffffffu, s, 1);
        s += __shfl_xor_sync(0xffffffffu, s, 2);
        s += __shfl_xor_sync(0xffffffffu, s, 4);
        if (sub == 0 && pos < 100) sh_dot[pos] = s;
    }
    __syncthreads();

    // --- bilinear combine for the 81 offsets, k = dxi*9 + dyi (x slow, y fast)
    if (t < 81) {
        int dxi = t / 9, dyi = t - dxi * 9;
        float xq = fminf(fmaxf(cx + (float)(dxi - 4), 0.f), (float)(Wl - 1));
        float yq = fminf(fmaxf(cy + (float)(dyi - 4), 0.f), (float)(Hl - 1));
        float x0f = floorf(xq), y0f = floorf(yq);
        float wx1 = xq - x0f,  wy1 = yq - y0f;
        float wx0 = 1.f - wx1, wy0 = 1.f - wy1;
        int t0x = min(max((int)x0f - ix + 4, 0), 9), t1x = min(t0x + 1, 9);
        int t0y = min(max((int)y0f - iy + 4, 0), 9), t1y = min(t0y + 1, 9);
        float v = wy0 * (wx0 * sh_dot[t0y * 10 + t0x] + wx1 * sh_dot[t0y * 10 + t1x])
                + wy1 * (wx0 * sh_dot[t1y * 10 + t0x] + wx1 * sh_dot[t1y * 10 + t1x]);
        out[ooff + t * (Hl * Wl) + p] = v * 0.08838834764831845f;  // 1/sqrt(128)
    }
}

// ---------------------------------------------------------------------------
extern "C" void kernel_launch(void* const* d_in, const int* in_sizes, int n_in,
                              void* d_out, int out_size) {
    const float* f1     = (const float*)d_in[0];
    const float* f2     = (const float*)d_in[1];
    const float* coords = (const float*)d_in[2];
    float* out = (float*)d_out;

    transpose_kernel<<<dim3(HW0 / 32, D128 / 32, 2), dim3(32, 32)>>>(f1, f2);
    pool_all_kernel<<<2016, 256>>>();
    // 148 * 56 = 8288 blocks cover 8160 work items with SM-contiguous mapping
    corr_kernel<<<8288, 128>>>(coords, out);
}

// round 4
// speedup vs baseline: 2.3645x; 1.1230x over previous
#include <cuda_runtime.h>
#include <cuda_fp16.h>

#define D128 128
#define H0 64
#define W0 96
#define HW0 (H0 * W0)   // 6144

// fp32 pyramids (HWD layout). L0 786432, L1 196608, L2 49152, L3 12288.
__device__ __align__(16) float  g_f1[1044480];
__device__ __align__(16) float  g_f2[1044480];
// half copy of f2 pyramid (quantized once per level from fp32)
__device__ __align__(16) __half g_f2h[1044480];

// ---------------------------------------------------------------------------
// Kernel 1: transpose (D, H*W) -> (H*W, D), vectorized. blockDim (8,32).
// Tile: 32 pixels x 32 channels. f2 path also writes half L0.
// ---------------------------------------------------------------------------
__global__ __launch_bounds__(256) void transpose_kernel(const float* __restrict__ f1,
                                                        const float* __restrict__ f2) {
    __shared__ float tile[32][33];
    int isF2 = blockIdx.z;
    const float* in  = isF2 ? f2 : f1;
    float*       out = isF2 ? g_f2 : g_f1;
    int pB = blockIdx.x * 32;   // pixel base
    int dB = blockIdx.y * 32;   // channel base
    int tx = threadIdx.x;       // 0..7
    int ty = threadIdx.y;       // 0..31

    // read: channel row (dB+ty), 4 consecutive pixels per thread
    float4 v = *(const float4*)(in + (dB + ty) * HW0 + pB + 4 * tx);
    tile[4 * tx + 0][ty] = v.x;
    tile[4 * tx + 1][ty] = v.y;
    tile[4 * tx + 2][ty] = v.z;
    tile[4 * tx + 3][ty] = v.w;
    __syncthreads();

    // write: pixel row (pB+ty), 4 consecutive channels per thread
    float4 w;
    w.x = tile[ty][4 * tx + 0];
    w.y = tile[ty][4 * tx + 1];
    w.z = tile[ty][4 * tx + 2];
    w.w = tile[ty][4 * tx + 3];
    int oidx = (pB + ty) * D128 + dB + 4 * tx;
    *(float4*)(out + oidx) = w;
    if (isF2) {
        __half2 h0 = __floats2half2_rn(w.x, w.y);
        __half2 h1 = __floats2half2_rn(w.z, w.w);
        uint2 packed = make_uint2(*(unsigned*)&h0, *(unsigned*)&h1);
        *(uint2*)(g_f2h + oidx) = packed;
    }
}

// ---------------------------------------------------------------------------
// Kernel 2: all pooled levels from transposed fp32 L0 (levels independent).
// f2 path also quantizes each level to half (single quantization per level).
// ---------------------------------------------------------------------------
__global__ void pool_all_kernel() {
    int i = blockIdx.x * 256 + threadIdx.x;
    if (i >= 2 * 258048) return;
    int isF2 = (i >= 258048);
    if (isF2) i -= 258048;
    float* base = isF2 ? g_f2 : g_f1;

    int lvl, ooff, idx;
    if (i < 196608)      { lvl = 1; ooff = 786432;  idx = i; }
    else if (i < 245760) { lvl = 2; ooff = 983040;  idx = i - 196608; }
    else                 { lvl = 3; ooff = 1032192; idx = i - 245760; }

    int c  = idx & 127;
    int pk = idx >> 7;
    int Wl = W0 >> lvl;
    int wo = pk % Wl, ho = pk / Wl;
    int s  = 1 << lvl;
    const float* in = base + ((ho * s) * W0 + wo * s) * D128 + c;
    float acc = 0.f;
    for (int dy = 0; dy < s; dy++)
        for (int dx = 0; dx < s; dx++)
            acc += in[(dy * W0 + dx) * D128];
    float r = acc * (1.0f / (float)(s * s));
    base[ooff + idx] = r;
    if (isF2) g_f2h[ooff + idx] = __float2half(r);
}

// ---------------------------------------------------------------------------
// Kernel 3: fused correlation lookup. f2 read as half (256 B / position),
// f1 fp32, fp32 accumulation. 8 lanes cooperate per position; 4 positions
// per warp per pass; 3x shfl_xor reduce.
// ---------------------------------------------------------------------------
__device__ __forceinline__ float dot8(uint4 r, float4 a, float4 b) {
    __half2* h = (__half2*)&r;
    float2 f0 = __half22float2(h[0]);
    float2 f1 = __half22float2(h[1]);
    float2 f2 = __half22float2(h[2]);
    float2 f3 = __half22float2(h[3]);
    float s = a.x * f0.x + a.y * f0.y;
    s += a.z * f1.x + a.w * f1.y;
    s += b.x * f2.x + b.y * f2.y;
    s += b.z * f3.x + b.w * f3.y;
    return s;
}

__global__ __launch_bounds__(128) void corr_kernel(const float* __restrict__ coords,
                                                   float* __restrict__ out) {
    // same-SM blocks (bid mod 148) get contiguous work ids -> L1 locality
    int g = (blockIdx.x % 148) * 56 + blockIdx.x / 148;
    if (g >= 8160) return;

    int lvl, p;
    if (g < 6144)       { lvl = 0; p = g; }
    else if (g < 7680)  { lvl = 1; p = g - 6144; }
    else if (g < 8064)  { lvl = 2; p = g - 7680; }
    else                { lvl = 3; p = g - 8064; }

    int loff, ooff;
    switch (lvl) {
        case 0:  loff = 0;       ooff = 0;      break;
        case 1:  loff = 786432;  ooff = 497664; break;
        case 2:  loff = 983040;  ooff = 622080; break;
        default: loff = 1032192; ooff = 653184; break;
    }
    const int Hl = H0 >> lvl, Wl = W0 >> lvl;
    int py = p / Wl, px = p - py * Wl;

    __shared__ float sh_c[2];
    __shared__ float sh_dot[112];

    int t    = threadIdx.x;
    int w    = t >> 5;
    int lane = t & 31;
    int sub  = lane & 7;   // chunk-owner within 8-lane group
    int quad = lane >> 3;  // position index within warp-pass

    // --- coords at this level (jax.image.resize linear antialias semantics)
    if (t < 2) {
        float c;
        if (lvl == 0) {
            c = coords[t * HW0 + p];
        } else {
            int   f    = 1 << lvl;
            float invf = 1.0f / (float)f;
            float sy = ((float)py + 0.5f) * (float)f - 0.5f;
            float sx = ((float)px + 0.5f) * (float)f - 0.5f;
            int jylo = max(0,      (int)floorf(sy - (float)f) + 1);
            int jyhi = min(H0 - 1, (int)floorf(sy + (float)f));
            int jxlo = max(0,      (int)floorf(sx - (float)f) + 1);
            int jxhi = min(W0 - 1, (int)floorf(sx + (float)f));
            float wyTot = 0.f, wxTot = 0.f;
            for (int j = jylo; j <= jyhi; j++) wyTot += 1.f - fabsf(sy - (float)j) * invf;
            for (int j = jxlo; j <= jxhi; j++) wxTot += 1.f - fabsf(sx - (float)j) * invf;
            const float* cc = coords + t * HW0;
            float acc = 0.f;
            for (int jy = jylo; jy <= jyhi; jy++) {
                float wy = 1.f - fabsf(sy - (float)jy) * invf;
                float ra = 0.f;
                for (int jx = jxlo; jx <= jxhi; jx++)
                    ra += (1.f - fabsf(sx - (float)jx) * invf) * cc[jy * W0 + jx];
                acc += wy * ra;
            }
            c = acc / (wyTot * wxTot) * invf;
        }
        sh_c[t] = c;
    }

    // --- f1 fp32 chunks for this lane: halves [sub*8, sub*8+8) and [64+sub*8, ...)
    const float4* f1v = (const float4*)(g_f1 + loff + p * D128);
    float4 a0 = f1v[2 * sub];
    float4 a1 = f1v[2 * sub + 1];
    float4 a2 = f1v[16 + 2 * sub];
    float4 a3 = f1v[17 + 2 * sub];

    __syncthreads();

    float cx = sh_c[0], cy = sh_c[1];
    int ix = (int)floorf(cx);
    int iy = (int)floorf(cy);

    const uint4* f2base = (const uint4*)(g_f2h + loff);  // 16B = 8 halves

    // --- 100 corner dots: 7 passes x (4 warps x 4 positions)
#pragma unroll
    for (int j = 0; j < 7; j++) {
        int pos  = j * 16 + w * 4 + quad;      // 0..111
        int posc = min(pos, 99);
        int ty = posc / 10, tx = posc - ty * 10;
        int gy = min(max(iy + ty - 4, 0), Hl - 1);
        int gx = min(max(ix + tx - 4, 0), Wl - 1);
        const uint4* q = f2base + (gy * Wl + gx) * 16;
        uint4 r0 = q[sub];
        uint4 r1 = q[8 + sub];
        float s = dot8(r0, a0, a1) + dot8(r1, a2, a3);
        s += __shfl_xor_sync(0xffffffffu, s, 1);
        s += __shfl_xor_sync(0xffffffffu, s, 2);
        s += __shfl_xor_sync(0xffffffffu, s, 4);
        if (sub == 0 && pos < 100) sh_dot[pos] = s;
    }
    __syncthreads();

    // --- bilinear combine, k = dxi*9 + dyi (x slow, y fast)
    if (t < 81) {
        int dxi = t / 9, dyi = t - dxi * 9;
        float xq = fminf(fmaxf(cx + (float)(dxi - 4), 0.f), (float)(Wl - 1));
        float yq = fminf(fmaxf(cy + (float)(dyi - 4), 0.f), (float)(Hl - 1));
        float x0f = floorf(xq), y0f = floorf(yq);
        float wx1 = xq - x0f,  wy1 = yq - y0f;
        float wx0 = 1.f - wx1, wy0 = 1.f - wy1;
        int t0x = min(max((int)x0f - ix + 4, 0), 9), t1x = min(t0x + 1, 9);
        int t0y = min(max((int)y0f - iy + 4, 0), 9), t1y = min(t0y + 1, 9);
        float v = wy0 * (wx0 * sh_dot[t0y * 10 + t0x] + wx1 * sh_dot[t0y * 10 + t1x])
                + wy1 * (wx0 * sh_dot[t1y * 10 + t0x] + wx1 * sh_dot[t1y * 10 + t1x]);
        out[ooff + t * (Hl * Wl) + p] = v * 0.08838834764831845f;  // 1/sqrt(128)
    }
}

// ---------------------------------------------------------------------------
extern "C" void kernel_launch(void* const* d_in, const int* in_sizes, int n_in,
                              void* d_out, int out_size) {
    const float* f1     = (const float*)d_in[0];
    const float* f2     = (const float*)d_in[1];
    const float* coords = (const float*)d_in[2];
    float* out = (float*)d_out;

    transpose_kernel<<<dim3(HW0 / 32, D128 / 32, 2), dim3(8, 32)>>>(f1, f2);
    pool_all_kernel<<<2016, 256>>>();
    corr_kernel<<<8288, 128>>>(coords, out);
}